// round 2
// baseline (speedup 1.0000x reference)
#include <cuda_runtime.h>
#include <math.h>

// ---------------------------------------------------------------------------
// TensorProductMultiLayerPerceptron — Round 1 (correct fp32 baseline)
//
// Formulation: contract (u,v) first.
//   S[r, x, w] = sum_{uv} A[r, uv] * P_seg(r)[x, uv, w]
// with A rows:
//   [0,128)    : A0[b]      = s1 (x) s2                      (P0)
//   [128,512)  : A1[b,j]    = s1 (x) v2_j                    (P1)
//   [512,896)  : A2[b,i]    = v1_i (x) s2                    (P2)
//   [896,1024) : A3[b]      = sum_i v1_i (x) v2_i            (P3)
//   [1024,1408): A4[b,k]    = cross(v1, v2)_k                (P4)
// Then t*[b,w,*] = sum_x hs[b,x] * S[row, x, w], combined/scaled into out.
// ---------------------------------------------------------------------------

#define BATCH 128
#define NROWS 1408

__device__ float g_hs[BATCH * 64];
__device__ float g_A[(size_t)NROWS * 4096];
__device__ float g_S[(size_t)NROWS * 4096];

__device__ __forceinline__ float gelu_tanh(float x) {
    // jax.nn.gelu default (approximate=True)
    float x3 = x * x * x;
    return 0.5f * x * (1.0f + tanhf(0.7978845608028654f * (x + 0.044715f * x3)));
}

// ---------------------------------------------------------------------------
// Kernel 1: MLP  emb(128x64) -> hs(128x64).  One block per batch row.
// ---------------------------------------------------------------------------
__global__ __launch_bounds__(256) void mlp_kernel(
    const float* __restrict__ emb,
    const float* __restrict__ W0,
    const float* __restrict__ W1,
    const float* __restrict__ W2,
    float phi_inv)
{
    __shared__ float sa[256];
    __shared__ float sb[256];
    int b = blockIdx.x;
    int t = threadIdx.x;

    if (t < 64) sa[t] = emb[b * 64 + t];
    __syncthreads();

    // Layer 1: 64 -> 256, scale 64^-0.5 = 1/8
    float acc = 0.0f;
#pragma unroll 8
    for (int k = 0; k < 64; k++) acc += sa[k] * W0[k * 256 + t];
    sb[t] = gelu_tanh(acc * 0.125f) * phi_inv;
    __syncthreads();

    // Layer 2: 256 -> 256, scale 1/16
    acc = 0.0f;
#pragma unroll 8
    for (int k = 0; k < 256; k++) acc += sb[k] * W1[k * 256 + t];
    float v2l = gelu_tanh(acc * 0.0625f) * phi_inv;
    __syncthreads();
    sa[t] = v2l;
    __syncthreads();

    // Layer 3: 256 -> 64, scale 1/16 ; then hs = h / 8
    if (t < 64) {
        acc = 0.0f;
#pragma unroll 8
        for (int k = 0; k < 256; k++) acc += sa[k] * W2[k * 64 + t];
        g_hs[b * 64 + t] = gelu_tanh(acc * 0.0625f) * phi_inv * 0.125f;
    }
}

// ---------------------------------------------------------------------------
// Kernel 2: build the 1408 x 4096 left matrix A.  One block per batch row.
// ---------------------------------------------------------------------------
__global__ __launch_bounds__(256) void prepA_kernel(
    const float* __restrict__ x1,
    const float* __restrict__ x2)
{
    __shared__ float s1[64], s2[64], v1[192], v2[192];
    int b = blockIdx.x;
    int t = threadIdx.x;

    float a1 = x1[b * 256 + t];
    float a2 = x2[b * 256 + t];
    if (t < 64) { s1[t] = a1; s2[t] = a2; }
    else        { v1[t - 64] = a1; v2[t - 64] = a2; }
    __syncthreads();

    size_t rA0 = (size_t)b * 4096;
    size_t rA1 = (size_t)(128 + b * 3) * 4096;
    size_t rA2 = (size_t)(512 + b * 3) * 4096;
    size_t rA3 = (size_t)(896 + b) * 4096;
    size_t rA4 = (size_t)(1024 + b * 3) * 4096;

#pragma unroll
    for (int it = 0; it < 16; it++) {
        int idx = t + it * 256;
        int u = idx >> 6;
        int v = idx & 63;
        float su = s1[u], sv = s2[v];
        float u0 = v1[u * 3 + 0], u1 = v1[u * 3 + 1], u2 = v1[u * 3 + 2];
        float w0 = v2[v * 3 + 0], w1 = v2[v * 3 + 1], w2 = v2[v * 3 + 2];

        g_A[rA0 + idx] = su * sv;                              // P0
        g_A[rA1 + idx]             = su * w0;                  // P1, j=0
        g_A[rA1 + 4096 + idx]      = su * w1;                  // j=1
        g_A[rA1 + 8192 + idx]      = su * w2;                  // j=2
        g_A[rA2 + idx]             = u0 * sv;                  // P2, i=0
        g_A[rA2 + 4096 + idx]      = u1 * sv;
        g_A[rA2 + 8192 + idx]      = u2 * sv;
        g_A[rA3 + idx] = u0 * w0 + u1 * w1 + u2 * w2;          // P3
        g_A[rA4 + idx]             = u1 * w2 - u2 * w1;        // P4 cross k=0
        g_A[rA4 + 4096 + idx]      = u2 * w0 - u0 * w2;        // k=1
        g_A[rA4 + 8192 + idx]      = u0 * w1 - u1 * w0;        // k=2
    }
}

// ---------------------------------------------------------------------------
// Kernel 3: the heavy GEMM.  grid = (22 row-tiles, 64 x-slices).
// Each block: C(64x64) = A_tile(64x4096) @ P[x](4096x64), written to g_S.
// ---------------------------------------------------------------------------
__global__ __launch_bounds__(256) void gemm_kernel(
    const float* __restrict__ p0, const float* __restrict__ p1,
    const float* __restrict__ p2, const float* __restrict__ p3,
    const float* __restrict__ p4)
{
    int tile = blockIdx.x;
    int x = blockIdx.y;

    int seg, r0;
    if (tile < 2)       { seg = 0; r0 = tile * 64; }
    else if (tile < 8)  { seg = 1; r0 = 128 + (tile - 2) * 64; }
    else if (tile < 14) { seg = 2; r0 = 512 + (tile - 8) * 64; }
    else if (tile < 16) { seg = 3; r0 = 896 + (tile - 14) * 64; }
    else                { seg = 4; r0 = 1024 + (tile - 16) * 64; }

    const float* P = (seg == 0) ? p0 : (seg == 1) ? p1 : (seg == 2) ? p2
                   : (seg == 3) ? p3 : p4;
    const float* Bp = P + (size_t)x * 262144;          // P[x] : 4096 x 64, contiguous
    const float* Ap = g_A + (size_t)r0 * 4096;

    __shared__ float As[16][64];   // As[k][m]
    __shared__ float Bs[16][64];   // Bs[k][w]

    int tid = threadIdx.x;
    int tx = tid & 15;             // output col group (w)
    int ty = tid >> 4;             // output row group (m)

    int arow = tid >> 2;           // A load: row 0..63
    int aq   = (tid & 3) * 4;      // A load: k quad
    int bk   = tid >> 4;           // B load: k 0..15
    int bq   = (tid & 15) * 4;     // B load: w quad

    float acc[4][4];
#pragma unroll
    for (int i = 0; i < 4; i++)
#pragma unroll
        for (int j = 0; j < 4; j++) acc[i][j] = 0.0f;

    float4 av = *(const float4*)(Ap + (size_t)arow * 4096 + aq);
    float4 bv = *(const float4*)(Bp + bk * 64 + bq);

    for (int k0 = 0; k0 < 4096; k0 += 16) {
        As[aq + 0][arow] = av.x;
        As[aq + 1][arow] = av.y;
        As[aq + 2][arow] = av.z;
        As[aq + 3][arow] = av.w;
        *(float4*)&Bs[bk][bq] = bv;
        __syncthreads();

        int kn = k0 + 16;
        if (kn < 4096) {
            av = *(const float4*)(Ap + (size_t)arow * 4096 + kn + aq);
            bv = *(const float4*)(Bp + (kn + bk) * 64 + bq);
        }

#pragma unroll
        for (int kk = 0; kk < 16; kk++) {
            float4 a = *(const float4*)&As[kk][ty * 4];
            float4 bb = *(const float4*)&Bs[kk][tx * 4];
            acc[0][0] += a.x * bb.x; acc[0][1] += a.x * bb.y;
            acc[0][2] += a.x * bb.z; acc[0][3] += a.x * bb.w;
            acc[1][0] += a.y * bb.x; acc[1][1] += a.y * bb.y;
            acc[1][2] += a.y * bb.z; acc[1][3] += a.y * bb.w;
            acc[2][0] += a.z * bb.x; acc[2][1] += a.z * bb.y;
            acc[2][2] += a.z * bb.z; acc[2][3] += a.z * bb.w;
            acc[3][0] += a.w * bb.x; acc[3][1] += a.w * bb.y;
            acc[3][2] += a.w * bb.z; acc[3][3] += a.w * bb.w;
        }
        __syncthreads();
    }

    size_t outBase = (size_t)r0 * 4096 + (size_t)x * 64;
#pragma unroll
    for (int i = 0; i < 4; i++) {
        *(float4*)&g_S[outBase + (size_t)(ty * 4 + i) * 4096 + tx * 4] =
            make_float4(acc[i][0], acc[i][1], acc[i][2], acc[i][3]);
    }
}

// ---------------------------------------------------------------------------
// Kernel 4: finalize.  t*[.] = sum_x hs[b,x] * S[row,x,w], combine + scale.
// out layout per batch row: [out0(64) | out1(192, w*3+c) | out2(192, w*3+k)]
// Note: ALPHA_01 = ALPHA_2*INV_SQ2 = 1/(64*sqrt(2)).
// ---------------------------------------------------------------------------
__global__ __launch_bounds__(448) void finalize_kernel(float* __restrict__ out)
{
    __shared__ float hs[64];
    int b = blockIdx.x;
    int t = threadIdx.x;
    if (t < 64) hs[t] = g_hs[b * 64 + t];
    __syncthreads();

    const float C = 0.011048543456039806f;       // 1/(64*sqrt(2))
    const float INV_SQ3 = 0.5773502691896258f;

    if (t < 64) {
        int w = t;
        size_t r0 = (size_t)b * 4096;
        size_t r3 = (size_t)(896 + b) * 4096;
        float acc = 0.0f;
#pragma unroll 4
        for (int x = 0; x < 64; x++)
            acc += hs[x] * (g_S[r0 + x * 64 + w] + INV_SQ3 * g_S[r3 + x * 64 + w]);
        out[b * 448 + w] = C * acc;
    } else if (t < 256) {
        int i = t - 64;
        int w = i / 3, c = i % 3;
        size_t r1 = (size_t)(128 + b * 3 + c) * 4096;
        size_t r2 = (size_t)(512 + b * 3 + c) * 4096;
        float acc = 0.0f;
#pragma unroll 4
        for (int x = 0; x < 64; x++)
            acc += hs[x] * (g_S[r1 + x * 64 + w] + g_S[r2 + x * 64 + w]);
        out[b * 448 + 64 + w * 3 + c] = C * acc;
    } else {
        int i = t - 256;
        int w = i / 3, k = i % 3;
        size_t r4 = (size_t)(1024 + b * 3 + k) * 4096;
        float acc = 0.0f;
#pragma unroll 4
        for (int x = 0; x < 64; x++)
            acc += hs[x] * g_S[r4 + x * 64 + w];
        out[b * 448 + 256 + w * 3 + k] = C * acc;
    }
}

// ---------------------------------------------------------------------------
// Host: replicate numpy's _PHI_C (gelu evaluated in float32, trapz in double).
// ---------------------------------------------------------------------------
static double host_phi_c()
{
    const double dz = 16.0 / 4000.0;
    const double inv_sqrt2pi = 0.3989422804014327;  // 1/sqrt(2*pi)
    double sum = 0.0, prev = 0.0;
    for (int i = 0; i <= 4000; i++) {
        double z = -8.0 + dz * (double)i;
        float xf = (float)z;
        float x3 = xf * xf * xf;
        float g = 0.5f * xf * (1.0f + tanhf(0.7978845608028654f * (xf + 0.044715f * x3)));
        double f = (double)g * (double)g * exp(-0.5 * z * z) * inv_sqrt2pi;
        if (i > 0) sum += 0.5 * (f + prev) * dz;
        prev = f;
    }
    return sqrt(sum);
}

extern "C" void kernel_launch(void* const* d_in, const int* in_sizes, int n_in,
                              void* d_out, int out_size)
{
    const float* emb = (const float*)d_in[0];
    const float* x1  = (const float*)d_in[1];
    const float* x2  = (const float*)d_in[2];
    const float* W0  = (const float*)d_in[3];
    const float* W1  = (const float*)d_in[4];
    const float* W2  = (const float*)d_in[5];
    const float* P0  = (const float*)d_in[6];
    const float* P1  = (const float*)d_in[7];
    const float* P2  = (const float*)d_in[8];
    const float* P3  = (const float*)d_in[9];
    const float* P4  = (const float*)d_in[10];
    float* out = (float*)d_out;

    float phi_inv = (float)(1.0 / host_phi_c());

    mlp_kernel<<<128, 256>>>(emb, W0, W1, W2, phi_inv);
    prepA_kernel<<<128, 256>>>(x1, x2);
    gemm_kernel<<<dim3(22, 64), 256>>>(P0, P1, P2, P3, P4);
    finalize_kernel<<<128, 448>>>(out);
}

// round 3
// speedup vs baseline: 3.2180x; 3.2180x over previous
#include <cuda_runtime.h>
#include <math.h>
#include <stdint.h>

// ---------------------------------------------------------------------------
// TensorProductMultiLayerPerceptron — Round 2: tf32 tensor-core GEMM
//
//   S[r, x, w] = sum_{uv} A[r, uv] * P_seg(r)[x, uv, w]
// A rows (1408 = 11 tiles of 128):
//   [0,128)    : A0[b]   = s1 (x) s2            (P0)
//   [128,512)  : A1[b,j] = s1 (x) v2_j          (P1)
//   [512,896)  : A2[b,i] = v1_i (x) s2          (P2)
//   [896,1024) : A3[b]   = sum_i v1_i (x) v2_i  (P3)
//   [1024,1408): A4[b,k] = cross(v1, v2)_k      (P4)
// ---------------------------------------------------------------------------

#define BATCH 128
#define NROWS 1408

__device__ float g_hs[BATCH * 64];
__device__ float g_A[(size_t)NROWS * 4096];
__device__ float g_S[(size_t)NROWS * 4096];

__device__ __forceinline__ float gelu_tanh(float x) {
    float x3 = x * x * x;
    return 0.5f * x * (1.0f + tanhf(0.7978845608028654f * (x + 0.044715f * x3)));
}

// ---------------------------------------------------------------------------
// Kernel 1: MLP  emb(128x64) -> hs(128x64)
// ---------------------------------------------------------------------------
__global__ __launch_bounds__(256) void mlp_kernel(
    const float* __restrict__ emb,
    const float* __restrict__ W0,
    const float* __restrict__ W1,
    const float* __restrict__ W2,
    float phi_inv)
{
    __shared__ float sa[256];
    __shared__ float sb[256];
    int b = blockIdx.x;
    int t = threadIdx.x;

    if (t < 64) sa[t] = emb[b * 64 + t];
    __syncthreads();

    float acc = 0.0f;
#pragma unroll 8
    for (int k = 0; k < 64; k++) acc += sa[k] * W0[k * 256 + t];
    sb[t] = gelu_tanh(acc * 0.125f) * phi_inv;
    __syncthreads();

    acc = 0.0f;
#pragma unroll 8
    for (int k = 0; k < 256; k++) acc += sb[k] * W1[k * 256 + t];
    float v2l = gelu_tanh(acc * 0.0625f) * phi_inv;
    __syncthreads();
    sa[t] = v2l;
    __syncthreads();

    if (t < 64) {
        acc = 0.0f;
#pragma unroll 8
        for (int k = 0; k < 256; k++) acc += sa[k] * W2[k * 64 + t];
        g_hs[b * 64 + t] = gelu_tanh(acc * 0.0625f) * phi_inv * 0.125f;
    }
}

// ---------------------------------------------------------------------------
// Kernel 2: build the 1408 x 4096 left matrix A
// ---------------------------------------------------------------------------
__global__ __launch_bounds__(256) void prepA_kernel(
    const float* __restrict__ x1,
    const float* __restrict__ x2)
{
    __shared__ float s1[64], s2[64], v1[192], v2[192];
    int b = blockIdx.x;
    int t = threadIdx.x;

    float a1 = x1[b * 256 + t];
    float a2 = x2[b * 256 + t];
    if (t < 64) { s1[t] = a1; s2[t] = a2; }
    else        { v1[t - 64] = a1; v2[t - 64] = a2; }
    __syncthreads();

    size_t rA0 = (size_t)b * 4096;
    size_t rA1 = (size_t)(128 + b * 3) * 4096;
    size_t rA2 = (size_t)(512 + b * 3) * 4096;
    size_t rA3 = (size_t)(896 + b) * 4096;
    size_t rA4 = (size_t)(1024 + b * 3) * 4096;

#pragma unroll
    for (int it = 0; it < 16; it++) {
        int idx = t + it * 256;
        int u = idx >> 6;
        int v = idx & 63;
        float su = s1[u], sv = s2[v];
        float u0 = v1[u * 3 + 0], u1 = v1[u * 3 + 1], u2 = v1[u * 3 + 2];
        float w0 = v2[v * 3 + 0], w1 = v2[v * 3 + 1], w2 = v2[v * 3 + 2];

        g_A[rA0 + idx] = su * sv;
        g_A[rA1 + idx]        = su * w0;
        g_A[rA1 + 4096 + idx] = su * w1;
        g_A[rA1 + 8192 + idx] = su * w2;
        g_A[rA2 + idx]        = u0 * sv;
        g_A[rA2 + 4096 + idx] = u1 * sv;
        g_A[rA2 + 8192 + idx] = u2 * sv;
        g_A[rA3 + idx] = u0 * w0 + u1 * w1 + u2 * w2;
        g_A[rA4 + idx]        = u1 * w2 - u2 * w1;
        g_A[rA4 + 4096 + idx] = u2 * w0 - u0 * w2;
        g_A[rA4 + 8192 + idx] = u0 * w1 - u1 * w0;
    }
}

// ---------------------------------------------------------------------------
// Kernel 3: tf32 tensor-core GEMM.
// grid = (11 m-tiles of 128 rows, 64 x-slices), 256 threads (8 warps, 4x2).
// Block tile: 128 x 64, K staged 16 at a time, 3-stage cp.async pipeline.
// ---------------------------------------------------------------------------
#define KS 16
#define STAGES 3
#define APAD 20   // 16 + 4  -> conflict-free A-fragment LDS
#define BPAD 72   // 64 + 8  -> conflict-free B-fragment LDS

__device__ __forceinline__ void cp_async16(void* smem, const void* gmem) {
    uint32_t s = (uint32_t)__cvta_generic_to_shared(smem);
    asm volatile("cp.async.cg.shared.global [%0], [%1], 16;\n" :: "r"(s), "l"(gmem));
}
__device__ __forceinline__ uint32_t f2tf32(float f) {
    uint32_t r;
    asm("cvt.rna.tf32.f32 %0, %1;\n" : "=r"(r) : "f"(f));
    return r;
}
__device__ __forceinline__ void mma_tf32(float* d, const uint32_t* a, const uint32_t* b) {
    asm volatile(
        "mma.sync.aligned.m16n8k8.row.col.f32.tf32.tf32.f32 "
        "{%0,%1,%2,%3}, {%4,%5,%6,%7}, {%8,%9}, {%0,%1,%2,%3};\n"
        : "+f"(d[0]), "+f"(d[1]), "+f"(d[2]), "+f"(d[3])
        : "r"(a[0]), "r"(a[1]), "r"(a[2]), "r"(a[3]), "r"(b[0]), "r"(b[1]));
}

__global__ __launch_bounds__(256) void gemm_tf32_kernel(
    const float* __restrict__ p0, const float* __restrict__ p1,
    const float* __restrict__ p2, const float* __restrict__ p3,
    const float* __restrict__ p4)
{
    __shared__ float As[STAGES][128][APAD];
    __shared__ float Bs[STAGES][KS][BPAD];

    int tile = blockIdx.x;           // 0..10
    int x = blockIdx.y;              // 0..63
    int r0 = tile * 128;

    const float* P = (r0 < 128) ? p0 : (r0 < 512) ? p1 : (r0 < 896) ? p2
                   : (r0 < 1024) ? p3 : p4;
    const float* Bp = P + (size_t)x * 262144;         // P[x]: 4096 x 64
    const float* Ap = g_A + (size_t)r0 * 4096;

    int tid = threadIdx.x;
    int lane = tid & 31;
    int warp = tid >> 5;
    int wm = warp >> 1;              // 0..3 (m)
    int wn = warp & 1;               // 0..1 (n)
    int g = lane >> 2;               // 0..7
    int tg = lane & 3;               // 0..3

    // A staging: 512 float4 -> 2 per thread: idx = tid, tid+256
    int am0 = tid >> 2;              // rows 0..63
    int ak0 = (tid & 3) * 4;
    // B staging: 256 float4 -> 1 per thread
    int bk = tid >> 4;               // 0..15
    int bn = (tid & 15) * 4;

    float acc[2][4][4];
#pragma unroll
    for (int i = 0; i < 2; i++)
#pragma unroll
        for (int j = 0; j < 4; j++)
#pragma unroll
            for (int k = 0; k < 4; k++) acc[i][j][k] = 0.0f;

    // Prologue: stages 0, 1
#pragma unroll
    for (int s = 0; s < STAGES - 1; s++) {
        int k0 = s * KS;
        cp_async16(&As[s][am0][ak0],      Ap + (size_t)am0 * 4096 + k0 + ak0);
        cp_async16(&As[s][am0 + 64][ak0], Ap + (size_t)(am0 + 64) * 4096 + k0 + ak0);
        cp_async16(&Bs[s][bk][bn],        Bp + (size_t)(k0 + bk) * 64 + bn);
        asm volatile("cp.async.commit_group;\n" ::: "memory");
    }

    const int NITER = 4096 / KS;     // 256
    for (int i = 0; i < NITER; i++) {
        int buf = i % STAGES;
        asm volatile("cp.async.wait_group %0;\n" :: "n"(STAGES - 2) : "memory");
        __syncthreads();

        int inext = i + STAGES - 1;
        if (inext < NITER) {
            int s = inext % STAGES;
            int k0 = inext * KS;
            cp_async16(&As[s][am0][ak0],      Ap + (size_t)am0 * 4096 + k0 + ak0);
            cp_async16(&As[s][am0 + 64][ak0], Ap + (size_t)(am0 + 64) * 4096 + k0 + ak0);
            cp_async16(&Bs[s][bk][bn],        Bp + (size_t)(k0 + bk) * 64 + bn);
        }
        asm volatile("cp.async.commit_group;\n" ::: "memory");

#pragma unroll
        for (int ks = 0; ks < 2; ks++) {
            int kk = ks * 8;
            uint32_t afr[2][4], bfr[4][2];
#pragma unroll
            for (int mf = 0; mf < 2; mf++) {
                int r = wm * 32 + mf * 16 + g;
                afr[mf][0] = f2tf32(As[buf][r][kk + tg]);
                afr[mf][1] = f2tf32(As[buf][r + 8][kk + tg]);
                afr[mf][2] = f2tf32(As[buf][r][kk + tg + 4]);
                afr[mf][3] = f2tf32(As[buf][r + 8][kk + tg + 4]);
            }
#pragma unroll
            for (int ch = 0; ch < 4; ch++) {
                int n = wn * 32 + ch * 8 + g;
                bfr[ch][0] = f2tf32(Bs[buf][kk + tg][n]);
                bfr[ch][1] = f2tf32(Bs[buf][kk + tg + 4][n]);
            }
#pragma unroll
            for (int mf = 0; mf < 2; mf++)
#pragma unroll
                for (int ch = 0; ch < 4; ch++)
                    mma_tf32(acc[mf][ch], afr[mf], bfr[ch]);
        }
    }

    // Epilogue: write C (128x64) into g_S[row][x*64 + w]
#pragma unroll
    for (int mf = 0; mf < 2; mf++) {
#pragma unroll
        for (int ch = 0; ch < 4; ch++) {
            int m = wm * 32 + mf * 16 + g;
            int w = wn * 32 + ch * 8 + tg * 2;
            size_t base = (size_t)(r0 + m) * 4096 + (size_t)x * 64 + w;
            *(float2*)&g_S[base] = make_float2(acc[mf][ch][0], acc[mf][ch][1]);
            *(float2*)&g_S[base + 8ull * 4096] = make_float2(acc[mf][ch][2], acc[mf][ch][3]);
        }
    }
}

// ---------------------------------------------------------------------------
// Kernel 4: finalize
// ---------------------------------------------------------------------------
__global__ __launch_bounds__(448) void finalize_kernel(float* __restrict__ out)
{
    __shared__ float hs[64];
    int b = blockIdx.x;
    int t = threadIdx.x;
    if (t < 64) hs[t] = g_hs[b * 64 + t];
    __syncthreads();

    const float C = 0.011048543456039806f;       // 1/(64*sqrt(2))
    const float INV_SQ3 = 0.5773502691896258f;

    if (t < 64) {
        int w = t;
        size_t r0 = (size_t)b * 4096;
        size_t r3 = (size_t)(896 + b) * 4096;
        float acc = 0.0f;
#pragma unroll 8
        for (int x = 0; x < 64; x++)
            acc += hs[x] * (g_S[r0 + x * 64 + w] + INV_SQ3 * g_S[r3 + x * 64 + w]);
        out[b * 448 + w] = C * acc;
    } else if (t < 256) {
        int i = t - 64;
        int w = i / 3, c = i % 3;
        size_t r1 = (size_t)(128 + b * 3 + c) * 4096;
        size_t r2 = (size_t)(512 + b * 3 + c) * 4096;
        float acc = 0.0f;
#pragma unroll 8
        for (int x = 0; x < 64; x++)
            acc += hs[x] * (g_S[r1 + x * 64 + w] + g_S[r2 + x * 64 + w]);
        out[b * 448 + 64 + w * 3 + c] = C * acc;
    } else {
        int i = t - 256;
        int w = i / 3, k = i % 3;
        size_t r4 = (size_t)(1024 + b * 3 + k) * 4096;
        float acc = 0.0f;
#pragma unroll 8
        for (int x = 0; x < 64; x++)
            acc += hs[x] * g_S[r4 + x * 64 + w];
        out[b * 448 + 256 + w * 3 + k] = C * acc;
    }
}

// ---------------------------------------------------------------------------
static double host_phi_c()
{
    const double dz = 16.0 / 4000.0;
    const double inv_sqrt2pi = 0.3989422804014327;
    double sum = 0.0, prev = 0.0;
    for (int i = 0; i <= 4000; i++) {
        double z = -8.0 + dz * (double)i;
        float xf = (float)z;
        float x3 = xf * xf * xf;
        float gg = 0.5f * xf * (1.0f + tanhf(0.7978845608028654f * (xf + 0.044715f * x3)));
        double f = (double)gg * (double)gg * exp(-0.5 * z * z) * inv_sqrt2pi;
        if (i > 0) sum += 0.5 * (f + prev) * dz;
        prev = f;
    }
    return sqrt(sum);
}

extern "C" void kernel_launch(void* const* d_in, const int* in_sizes, int n_in,
                              void* d_out, int out_size)
{
    const float* emb = (const float*)d_in[0];
    const float* x1  = (const float*)d_in[1];
    const float* x2  = (const float*)d_in[2];
    const float* W0  = (const float*)d_in[3];
    const float* W1  = (const float*)d_in[4];
    const float* W2  = (const float*)d_in[5];
    const float* P0  = (const float*)d_in[6];
    const float* P1  = (const float*)d_in[7];
    const float* P2  = (const float*)d_in[8];
    const float* P3  = (const float*)d_in[9];
    const float* P4  = (const float*)d_in[10];
    float* out = (float*)d_out;

    float phi_inv = (float)(1.0 / host_phi_c());

    mlp_kernel<<<128, 256>>>(emb, W0, W1, W2, phi_inv);
    prepA_kernel<<<128, 256>>>(x1, x2);
    gemm_tf32_kernel<<<dim3(11, 64), 256>>>(P0, P1, P2, P3, P4);
    finalize_kernel<<<128, 448>>>(out);
}

// round 6
// speedup vs baseline: 5.7812x; 1.7965x over previous
#include <cuda_runtime.h>
#include <cuda_fp16.h>
#include <math.h>
#include <stdint.h>

// ---------------------------------------------------------------------------
// TensorProductMultiLayerPerceptron — Round 5: fp16 mma.sync GEMM (compile fix)
//
//   S[r, x, w] = sum_{uv} A[r, uv] * P_seg(r)[x, uv, w]
//   T[r, w]    = sum_x hs[b(r), x] * S[r, x, w]
// A rows (1408 = 11 tiles of 128):
//   [0,128)    : A0[b]   = s1 (x) s2            (P0)
//   [128,512)  : A1[b,j] = s1 (x) v2_j          (P1)
//   [512,896)  : A2[b,i] = v1_i (x) s2          (P2)
//   [896,1024) : A3[b]   = sum_i v1_i (x) v2_i  (P3)
//   [1024,1408): A4[b,k] = cross(v1, v2)_k      (P4)
// GEMM: block tile 128(m) x 128(n = 2 x-slices) x K, K split in 2 halves.
// Epilogue: hs-weighted per-(kz,x) partials -> reduce -> combine.
// ---------------------------------------------------------------------------

#define BATCH 128
#define NROWS 1408

__device__ __half g_Ah[(size_t)NROWS * 4096];
__device__ float  g_hs[BATCH * 64];
__device__ float  g_part[(size_t)128 * NROWS * 64];   // [kz*64+x][r][w]
__device__ float  g_T[(size_t)NROWS * 64];

// ---------------- helpers ----------------
__device__ __forceinline__ uint32_t smem_u32(const void* p) {
    uint32_t a;
    asm("{ .reg .u64 t; cvta.to.shared.u64 t, %1; cvt.u32.u64 %0, t; }"
        : "=r"(a) : "l"(p));
    return a;
}
__device__ __forceinline__ void cp16(uint32_t s, const void* g) {
    asm volatile("cp.async.cg.shared.global [%0], [%1], 16;\n" :: "r"(s), "l"(g));
}
#define CP_COMMIT() asm volatile("cp.async.commit_group;\n" ::: "memory")
#define CP_WAIT(n)  asm volatile("cp.async.wait_group %0;\n" :: "n"(n) : "memory")

#define LDSM4(r, addr) \
    asm volatile("ldmatrix.sync.aligned.m8n8.x4.shared.b16 {%0,%1,%2,%3}, [%4];" \
        : "=r"((r)[0]), "=r"((r)[1]), "=r"((r)[2]), "=r"((r)[3]) : "r"(addr))
#define LDSM4T(r, addr) \
    asm volatile("ldmatrix.sync.aligned.m8n8.x4.trans.shared.b16 {%0,%1,%2,%3}, [%4];" \
        : "=r"((r)[0]), "=r"((r)[1]), "=r"((r)[2]), "=r"((r)[3]) : "r"(addr))
#define MMA16816(d, a, b0, b1) \
    asm volatile("mma.sync.aligned.m16n8k16.row.col.f32.f16.f16.f32 " \
        "{%0,%1,%2,%3},{%4,%5,%6,%7},{%8,%9},{%0,%1,%2,%3};" \
        : "+f"((d)[0]), "+f"((d)[1]), "+f"((d)[2]), "+f"((d)[3]) \
        : "r"((a)[0]), "r"((a)[1]), "r"((a)[2]), "r"((a)[3]), "r"(b0), "r"(b1))

__device__ __forceinline__ uint32_t pack_h2(float a, float b) {
    __half2 h = __floats2half2_rn(a, b);
    return *reinterpret_cast<uint32_t*>(&h);
}

__device__ __forceinline__ float gelu_tanh(float x) {
    float x3 = x * x * x;
    return 0.5f * x * (1.0f + tanhf(0.7978845608028654f * (x + 0.044715f * x3)));
}
__device__ __forceinline__ int b_of_r(int r) {
    if (r < 128)  return r;
    if (r < 512)  return (r - 128) / 3;
    if (r < 896)  return (r - 512) / 3;
    if (r < 1024) return r - 896;
    return (r - 1024) / 3;
}

// ---------------------------------------------------------------------------
// Kernel 1: MLP  emb(128x64) -> hs(128x64)
// ---------------------------------------------------------------------------
__global__ __launch_bounds__(256) void mlp_kernel(
    const float* __restrict__ emb, const float* __restrict__ W0,
    const float* __restrict__ W1, const float* __restrict__ W2, float phi_inv)
{
    __shared__ float sa[256];
    __shared__ float sb[256];
    int b = blockIdx.x;
    int t = threadIdx.x;

    if (t < 64) sa[t] = emb[b * 64 + t];
    __syncthreads();

    float acc = 0.0f;
#pragma unroll 8
    for (int k = 0; k < 64; k++) acc += sa[k] * W0[k * 256 + t];
    sb[t] = gelu_tanh(acc * 0.125f) * phi_inv;
    __syncthreads();

    acc = 0.0f;
#pragma unroll 8
    for (int k = 0; k < 256; k++) acc += sb[k] * W1[k * 256 + t];
    float v2l = gelu_tanh(acc * 0.0625f) * phi_inv;
    __syncthreads();
    sa[t] = v2l;
    __syncthreads();

    if (t < 64) {
        acc = 0.0f;
#pragma unroll 8
        for (int k = 0; k < 256; k++) acc += sa[k] * W2[k * 64 + t];
        g_hs[b * 64 + t] = gelu_tanh(acc * 0.0625f) * phi_inv * 0.125f;
    }
}

// ---------------------------------------------------------------------------
// Kernel 2: build A as fp16 (half2 stores)
// ---------------------------------------------------------------------------
__global__ __launch_bounds__(256) void prepA_kernel(
    const float* __restrict__ x1, const float* __restrict__ x2)
{
    __shared__ float s1[64], s2[64], v1[192], v2[192];
    int b = blockIdx.x;
    int t = threadIdx.x;

    float a1 = x1[b * 256 + t];
    float a2 = x2[b * 256 + t];
    if (t < 64) { s1[t] = a1; s2[t] = a2; }
    else        { v1[t - 64] = a1; v2[t - 64] = a2; }
    __syncthreads();

    __half2* gA2 = (__half2*)g_Ah;
    int rA0 = b;
    int rA1 = 128 + b * 3;
    int rA2 = 512 + b * 3;
    int rA3 = 896 + b;
    int rA4 = 1024 + b * 3;

#pragma unroll
    for (int it = 0; it < 8; it++) {
        int base = it * 512 + t * 2;
        int u = base >> 6;
        int vv = base & 63;
        int col = base >> 1;            // half2 column 0..2047

        float su = s1[u];
        float sa = s2[vv], sb2 = s2[vv + 1];
        float u0 = v1[u * 3 + 0], u1 = v1[u * 3 + 1], u2 = v1[u * 3 + 2];
        float a0 = v2[vv * 3 + 0], a1v = v2[vv * 3 + 1], a2v = v2[vv * 3 + 2];
        float b0 = v2[vv * 3 + 3], b1v = v2[vv * 3 + 4], b2v = v2[vv * 3 + 5];

        gA2[(size_t)rA0 * 2048 + col] = __floats2half2_rn(su * sa, su * sb2);
        gA2[(size_t)(rA1 + 0) * 2048 + col] = __floats2half2_rn(su * a0,  su * b0);
        gA2[(size_t)(rA1 + 1) * 2048 + col] = __floats2half2_rn(su * a1v, su * b1v);
        gA2[(size_t)(rA1 + 2) * 2048 + col] = __floats2half2_rn(su * a2v, su * b2v);
        gA2[(size_t)(rA2 + 0) * 2048 + col] = __floats2half2_rn(u0 * sa, u0 * sb2);
        gA2[(size_t)(rA2 + 1) * 2048 + col] = __floats2half2_rn(u1 * sa, u1 * sb2);
        gA2[(size_t)(rA2 + 2) * 2048 + col] = __floats2half2_rn(u2 * sa, u2 * sb2);
        gA2[(size_t)rA3 * 2048 + col] = __floats2half2_rn(
            u0 * a0 + u1 * a1v + u2 * a2v, u0 * b0 + u1 * b1v + u2 * b2v);
        gA2[(size_t)(rA4 + 0) * 2048 + col] = __floats2half2_rn(
            u1 * a2v - u2 * a1v, u1 * b2v - u2 * b1v);
        gA2[(size_t)(rA4 + 1) * 2048 + col] = __floats2half2_rn(
            u2 * a0 - u0 * a2v, u2 * b0 - u0 * b2v);
        gA2[(size_t)(rA4 + 2) * 2048 + col] = __floats2half2_rn(
            u0 * a1v - u1 * a0, u0 * b1v - u1 * b0);
    }
}

// ---------------------------------------------------------------------------
// Kernel 3: fp16 mma.sync GEMM.  grid = (11, 32, 2), 256 threads (8 warps 4x2).
// Stage: A fp16 [128][32] (8KB, swz) | Braw fp32 [32][128] (16KB) |
//        Bh fp16 [32][128] (8KB, swz).  3 stages = 96KB dynamic smem.
// ---------------------------------------------------------------------------
#define SSTRIDE  32768
#define OFF_BRAW 8192
#define OFF_BH   24576
#define NSLAB    64        // K-half 2048 / 32

extern __shared__ char dsm[];

__global__ void __launch_bounds__(256, 2) gemm_fp16_kernel(
    const float* __restrict__ p0, const float* __restrict__ p1,
    const float* __restrict__ p2, const float* __restrict__ p3,
    const float* __restrict__ p4)
{
    int t = threadIdx.x;
    int lane = t & 31;
    int warp = t >> 5;
    int wm = warp >> 1;          // 0..3
    int wn = warp & 1;           // 0..1
    int tile = blockIdx.x;       // 0..10
    int xp = blockIdx.y;         // 0..31
    int kz = blockIdx.z;         // 0..1
    int r0 = tile * 128;

    const float* P = (r0 < 128) ? p0 : (r0 < 512) ? p1 : (r0 < 896) ? p2
                   : (r0 < 1024) ? p3 : p4;
    const float* Bg = P + (size_t)(xp * 2) * 262144 + (size_t)kz * 2048 * 64;
    const __half* Ag = g_Ah + (size_t)r0 * 4096 + kz * 2048;

    uint32_t sb = smem_u32(dsm);

    // --- loader coordinates ---
    // A: 512 chunks of 16B; idx = t + j*256: m = idx>>2, c = idx&3
    uint32_t aoff[2];
    const __half* asrc[2];
#pragma unroll
    for (int j = 0; j < 2; j++) {
        int idx = t + j * 256;
        int m = idx >> 2, c = idx & 3;
        aoff[j] = (uint32_t)(m * 64 + ((c ^ ((m >> 1) & 3)) << 4));
        asrc[j] = Ag + (size_t)m * 4096 + c * 8;
    }
    // B raw: 1024 chunks; idx = t + j*256: k = idx>>5, cc = idx&31
    uint32_t boff[4];
    const float* bsrc[4];
#pragma unroll
    for (int j = 0; j < 4; j++) {
        int idx = t + j * 256;
        int k = idx >> 5, cc = idx & 31;
        boff[j] = (uint32_t)(OFF_BRAW + k * 512 + cc * 16);
        bsrc[j] = Bg + (size_t)(cc >> 4) * 262144 + (size_t)k * 64 + (cc & 15) * 4;
    }

    // prologue: stages 0, 1
#pragma unroll
    for (int s = 0; s < 2; s++) {
        uint32_t st = sb + s * SSTRIDE;
        int k0 = s * 32;
#pragma unroll
        for (int j = 0; j < 2; j++) cp16(st + aoff[j], asrc[j] + k0);
#pragma unroll
        for (int j = 0; j < 4; j++) cp16(st + boff[j], bsrc[j] + (size_t)k0 * 64);
        CP_COMMIT();
    }

    float acc[2][8][4];
#pragma unroll
    for (int i = 0; i < 2; i++)
#pragma unroll
        for (int j = 0; j < 8; j++)
#pragma unroll
            for (int k = 0; k < 4; k++) acc[i][j][k] = 0.0f;

    // per-lane fragment coordinates
    int arow_l = (lane & 7) + ((lane >> 3) & 1) * 8;     // row within m16 tile
    int ak_hi  = (lane >> 4) & 1;                         // +8 k for lanes 16-31
    int brow_l = arow_l;                                  // k within k16 tile
    int bn_hi  = ((lane >> 4) & 1) * 8;                   // +8 n for lanes 16-31

#pragma unroll 1
    for (int i = 0; i < NSLAB; i++) {
        int s = i % 3;
        uint32_t st = sb + s * SSTRIDE;

        CP_WAIT(1);
        __syncthreads();

        // issue loads for slab i+2 into stage (i+2)%3
        if (i + 2 < NSLAB) {
            uint32_t st2 = sb + ((i + 2) % 3) * SSTRIDE;
            int k0 = (i + 2) * 32;
#pragma unroll
            for (int j = 0; j < 2; j++) cp16(st2 + aoff[j], asrc[j] + k0);
#pragma unroll
            for (int j = 0; j < 4; j++) cp16(st2 + boff[j], bsrc[j] + (size_t)k0 * 64);
        }
        CP_COMMIT();

        // convert Braw -> Bh (swizzled fp16)
#pragma unroll
        for (int j = 0; j < 2; j++) {
            int tau = t + j * 256;
            int k = tau >> 4, c = tau & 15;
            const float4* src = (const float4*)(dsm + s * SSTRIDE + OFF_BRAW
                                                + k * 512 + c * 32);
            float4 f0 = src[0], f1 = src[1];
            uint4* dst = (uint4*)(dsm + s * SSTRIDE + OFF_BH
                                  + k * 256 + ((c ^ (k & 7)) << 4));
            *dst = make_uint4(pack_h2(f0.x, f0.y), pack_h2(f0.z, f0.w),
                              pack_h2(f1.x, f1.y), pack_h2(f1.z, f1.w));
        }
        __syncthreads();

        // MMA over this slab (k32 = 2 x k16)
#pragma unroll
        for (int kk = 0; kk < 2; kk++) {
            uint32_t a0[4], a1[4];
            {
                int row = wm * 32 + arow_l;
                int c = kk * 2 + ak_hi;
                LDSM4(a0, st + row * 64 + ((c ^ ((row >> 1) & 3)) << 4));
                row += 16;
                LDSM4(a1, st + row * 64 + ((c ^ ((row >> 1) & 3)) << 4));
            }
            int krow = kk * 16 + brow_l;
            uint32_t bbase = st + OFF_BH + krow * 256;
            uint32_t kx = (uint32_t)(krow & 7);
#pragma unroll
            for (int nj = 0; nj < 4; nj++) {
                int n = wn * 64 + nj * 16 + bn_hi;
                uint32_t c = (uint32_t)(n >> 3);
                uint32_t bfr[4];
                LDSM4T(bfr, bbase + ((c ^ kx) << 4));
                MMA16816(acc[0][nj * 2],     a0, bfr[0], bfr[1]);
                MMA16816(acc[0][nj * 2 + 1], a0, bfr[2], bfr[3]);
                MMA16816(acc[1][nj * 2],     a1, bfr[0], bfr[1]);
                MMA16816(acc[1][nj * 2 + 1], a1, bfr[2], bfr[3]);
            }
        }
    }

    // ---- epilogue: hs-weighted, race-free partials ----
    int g = lane >> 2, tg = lane & 3;
    int x = xp * 2 + wn;
    size_t pbase = (size_t)(kz * 64 + x) * NROWS * 64;
#pragma unroll
    for (int mi = 0; mi < 2; mi++) {
        int r_top = r0 + wm * 32 + mi * 16 + g;
        int r_bot = r_top + 8;
        float h_top = g_hs[b_of_r(r_top) * 64 + x];
        float h_bot = g_hs[b_of_r(r_bot) * 64 + x];
#pragma unroll
        for (int ni = 0; ni < 8; ni++) {
            int w = ni * 8 + tg * 2;
            *(float2*)&g_part[pbase + (size_t)r_top * 64 + w] =
                make_float2(h_top * acc[mi][ni][0], h_top * acc[mi][ni][1]);
            *(float2*)&g_part[pbase + (size_t)r_bot * 64 + w] =
                make_float2(h_bot * acc[mi][ni][2], h_bot * acc[mi][ni][3]);
        }
    }
}

// ---------------------------------------------------------------------------
// Kernel 4: reduce partials over 128 (kz,x) slices -> g_T
// ---------------------------------------------------------------------------
__global__ __launch_bounds__(256) void reduceT_kernel()
{
    int idx = blockIdx.x * 256 + threadIdx.x;   // 0 .. 90111
    float acc = 0.0f;
#pragma unroll 8
    for (int p = 0; p < 128; p++)
        acc += g_part[(size_t)p * (NROWS * 64) + idx];
    g_T[idx] = acc;
}

// ---------------------------------------------------------------------------
// Kernel 5: combine to output
// ---------------------------------------------------------------------------
__global__ __launch_bounds__(448) void combine_kernel(float* __restrict__ out)
{
    int b = blockIdx.x;
    int t = threadIdx.x;
    const float C = 0.011048543456039806f;       // 1/(64*sqrt(2))
    const float INV_SQ3 = 0.5773502691896258f;

    if (t < 64) {
        int w = t;
        out[b * 448 + w] = C * (g_T[(size_t)b * 64 + w]
                              + INV_SQ3 * g_T[(size_t)(896 + b) * 64 + w]);
    } else if (t < 256) {
        int i = t - 64;
        int w = i / 3, c = i % 3;
        out[b * 448 + 64 + w * 3 + c] =
            C * (g_T[(size_t)(128 + b * 3 + c) * 64 + w]
               + g_T[(size_t)(512 + b * 3 + c) * 64 + w]);
    } else {
        int i = t - 256;
        int w = i / 3, k = i % 3;
        out[b * 448 + 256 + w * 3 + k] =
            C * g_T[(size_t)(1024 + b * 3 + k) * 64 + w];
    }
}

// ---------------------------------------------------------------------------
static double host_phi_c()
{
    const double dz = 16.0 / 4000.0;
    const double inv_sqrt2pi = 0.3989422804014327;
    double sum = 0.0, prev = 0.0;
    for (int i = 0; i <= 4000; i++) {
        double z = -8.0 + dz * (double)i;
        float xf = (float)z;
        float x3 = xf * xf * xf;
        float gg = 0.5f * xf * (1.0f + tanhf(0.7978845608028654f * (xf + 0.044715f * x3)));
        double f = (double)gg * (double)gg * exp(-0.5 * z * z) * inv_sqrt2pi;
        if (i > 0) sum += 0.5 * (f + prev) * dz;
        prev = f;
    }
    return sqrt(sum);
}

#define GEMM_DSMEM (3 * SSTRIDE)   // 98304

extern "C" void kernel_launch(void* const* d_in, const int* in_sizes, int n_in,
                              void* d_out, int out_size)
{
    const float* emb = (const float*)d_in[0];
    const float* x1  = (const float*)d_in[1];
    const float* x2  = (const float*)d_in[2];
    const float* W0  = (const float*)d_in[3];
    const float* W1  = (const float*)d_in[4];
    const float* W2  = (const float*)d_in[5];
    const float* P0  = (const float*)d_in[6];
    const float* P1  = (const float*)d_in[7];
    const float* P2  = (const float*)d_in[8];
    const float* P3  = (const float*)d_in[9];
    const float* P4  = (const float*)d_in[10];
    float* out = (float*)d_out;

    float phi_inv = (float)(1.0 / host_phi_c());

    cudaFuncSetAttribute(gemm_fp16_kernel,
                         cudaFuncAttributeMaxDynamicSharedMemorySize, GEMM_DSMEM);

    mlp_kernel<<<128, 256>>>(emb, W0, W1, W2, phi_inv);
    prepA_kernel<<<128, 256>>>(x1, x2);
    gemm_fp16_kernel<<<dim3(11, 32, 2), 256, GEMM_DSMEM>>>(P0, P1, P2, P3, P4);
    reduceT_kernel<<<352, 256>>>();
    combine_kernel<<<128, 448>>>(out);
}